// round 7
// baseline (speedup 1.0000x reference)
#include <cuda_runtime.h>
#include <cuda_fp16.h>
#include <cstdint>
#include <math.h>

// ---------------- problem constants ----------------
#define NTOK   65536
#define CDIM   512
#define NWIN   512
#define LWIN   128
#define NHEAD  8
#define HDIM   64

// ---------------- scratch ----------------
__device__ __half g_x16[(size_t)NTOK * CDIM];   // windowed x, fp16
__device__ __half g_q16[(size_t)NTOK * CDIM];   // Q pre-scaled by 0.125
__device__ __half g_k16[(size_t)NTOK * CDIM];
__device__ __half g_v16[(size_t)NTOK * CDIM];
__device__ __half g_ao[(size_t)NTOK * CDIM];    // attention output (windowed rows)
__device__ __half g_w16[(size_t)4 * CDIM * CDIM];

// windowed row m -> natural token index n
__device__ __forceinline__ int win_to_src(int m) {
    int w = m >> 7, l = m & 127;
    int w1 = w & 7, h1 = (w >> 3) & 7, f1 = w >> 6;
    int iw = l & 7, ih = (l >> 3) & 7, t  = l >> 6;
    return ((f1 * 2 + t) << 12) + ((h1 * 8 + ih) << 6) + (w1 * 8 + iw);
}

// ---------------- PTX helpers ----------------
__device__ __forceinline__ uint32_t smem_u32(const void* p) {
    uint32_t a;
    asm("{ .reg .u64 t; cvta.to.shared.u64 t, %1; cvt.u32.u64 %0, t; }" : "=r"(a) : "l"(p));
    return a;
}
#define CP16(dst, src) \
    asm volatile("cp.async.cg.shared.global [%0], [%1], 16;" :: "r"(dst), "l"(src))
#define CP_COMMIT() asm volatile("cp.async.commit_group;" ::: "memory")
#define CP_WAIT1()  asm volatile("cp.async.wait_group 1;" ::: "memory")
#define CP_WAIT0()  asm volatile("cp.async.wait_group 0;" ::: "memory")

#define LDSM4(r0, r1, r2, r3, a) \
    asm volatile("ldmatrix.sync.aligned.m8n8.x4.shared.b16 {%0,%1,%2,%3}, [%4];" \
                 : "=r"(r0), "=r"(r1), "=r"(r2), "=r"(r3) : "r"(a))
#define LDSM2(r0, r1, a) \
    asm volatile("ldmatrix.sync.aligned.m8n8.x2.shared.b16 {%0,%1}, [%2];" \
                 : "=r"(r0), "=r"(r1) : "r"(a))
#define LDSM4T(r0, r1, r2, r3, a) \
    asm volatile("ldmatrix.sync.aligned.m8n8.x4.trans.shared.b16 {%0,%1,%2,%3}, [%4];" \
                 : "=r"(r0), "=r"(r1), "=r"(r2), "=r"(r3) : "r"(a))

#define MMA_F16(c, a, b) \
    asm volatile("mma.sync.aligned.m16n8k16.row.col.f32.f16.f16.f32 " \
                 "{%0,%1,%2,%3}, {%4,%5,%6,%7}, {%8,%9}, {%0,%1,%2,%3};" \
                 : "+f"((c)[0]), "+f"((c)[1]), "+f"((c)[2]), "+f"((c)[3]) \
                 : "r"((a)[0]), "r"((a)[1]), "r"((a)[2]), "r"((a)[3]), \
                   "r"((b)[0]), "r"((b)[1]))

__device__ __forceinline__ uint32_t pkh(float a, float b) {
    __half2 h = __float22half2_rn(make_float2(a, b));
    return *reinterpret_cast<uint32_t*>(&h);
}

// =====================================================================
// conversion kernels
// =====================================================================
__global__ void convert_x(const float* __restrict__ x) {
    int idx = blockIdx.x * 256 + threadIdx.x;
    int m = idx >> 7, q = idx & 127;
    int n = win_to_src(m);
    float4 v = *(const float4*)(x + (size_t)n * CDIM + q * 4);
    __half* dst = g_x16 + (size_t)m * CDIM + q * 4;
    *(__half2*)(dst)     = __float22half2_rn(make_float2(v.x, v.y));
    *(__half2*)(dst + 2) = __float22half2_rn(make_float2(v.z, v.w));
}

__global__ void convert_w(const float* __restrict__ Wq, const float* __restrict__ Wk,
                          const float* __restrict__ Wv, const float* __restrict__ Wo) {
    int sel = blockIdx.x >> 8;
    int rem = (blockIdx.x & 255) * 256 + threadIdx.x;
    const float* W = (sel == 0) ? Wq : (sel == 1) ? Wk : (sel == 2) ? Wv : Wo;
    float4 v = *(const float4*)(W + (size_t)rem * 4);
    __half* dst = g_w16 + (size_t)sel * CDIM * CDIM + (size_t)rem * 4;
    *(__half2*)(dst)     = __float22half2_rn(make_float2(v.x, v.y));
    *(__half2*)(dst + 2) = __float22half2_rn(make_float2(v.z, v.w));
}

// =====================================================================
// A-resident GEMM engine.
// CTA: 512 threads (16 warps: 2m x 8n), tile 128x256 per output pass.
// A (128x512 fp16) resident in smem (8 chunks of 128x64, SW128 XOR swizzle,
// 128B rows). B streams in a 3-stage ring of 256x64 chunks.
// One barrier per chunk; cp.async depth 2.
// =====================================================================
#define ACH_B   16384                       // A chunk bytes (128 x 128B)
#define A_BYTES (8 * ACH_B)                 // 131072
#define BCH_B   32768                       // B chunk bytes (256 x 128B)
#define SB_OFF(s) (A_BYTES + (s) * BCH_B)
#define FUSED_SMEM_BYTES (A_BYTES + 3 * BCH_B)   // 229376

// swizzled 16B-slot offset within a 128B-row tile
__device__ __forceinline__ uint32_t swz(int row, int colByte) {
    return (uint32_t)(row * 128 + (colByte ^ ((row & 7) << 4)));
}

// prefetch one "global chunk" g: B chunk (matrix g>>3, kchunk g&7) into stage g%3;
// if g < 8 also A chunk g. Commits one group.
__device__ __forceinline__ void fused_prefetch(uint32_t smem,
                                               const __half* __restrict__ A,
                                               const __half* __restrict__ Wbase,
                                               size_t wstride, int g) {
    const int tid = threadIdx.x;
    const int c = g & 7;
    if (g < 8) {
#pragma unroll
        for (int i = 0; i < 2; i++) {               // 1024 slots / 512 threads
            int idx = tid + i * 512;
            int row = idx >> 3, c8 = idx & 7;
            CP16(smem + c * ACH_B + swz(row, c8 * 16),
                 A + (size_t)row * CDIM + c * 64 + c8 * 8);
        }
    }
    const __half* B = Wbase + (size_t)(g >> 3) * wstride;
    const uint32_t sb = smem + SB_OFF(g % 3);
#pragma unroll
    for (int i = 0; i < 4; i++) {                   // 2048 slots / 512 threads
        int idx = tid + i * 512;
        int row = idx >> 3, c8 = idx & 7;
        CP16(sb + swz(row, c8 * 16),
             B + (size_t)row * CDIM + c * 64 + c8 * 8);
    }
    CP_COMMIT();
}

// compute one chunk: acc += A_chunk(c) * B_stage^T
__device__ __forceinline__ void fused_compute(uint32_t smem, int c, int stage,
                                              float acc[4][4][4]) {
    const int tid  = threadIdx.x;
    const int lane = tid & 31;
    const int wid  = tid >> 5;
    const int wm   = wid >> 3;      // 0..1
    const int wn   = wid & 7;       // 0..7
    const uint32_t mask = (uint32_t)((lane & 7) << 4);

    const uint32_t aBase = smem + c * ACH_B + (uint32_t)(wm * 64 + (lane & 15)) * 128;
    const uint32_t aCol0 = (uint32_t)((lane >> 4) * 16);
    const uint32_t bBase = smem + SB_OFF(stage) + (uint32_t)(wn * 32 + (lane & 7)) * 128;
    const uint32_t bCol0 = (uint32_t)(((lane >> 3) & 1) * 16);

#pragma unroll
    for (int ks = 0; ks < 4; ks++) {
        uint32_t a[4][4], b[4][2];
#pragma unroll
        for (int mf = 0; mf < 4; mf++)
            LDSM4(a[mf][0], a[mf][1], a[mf][2], a[mf][3],
                  aBase + mf * (16 * 128) + ((aCol0 + ks * 32) ^ mask));
#pragma unroll
        for (int nf = 0; nf < 4; nf++)
            LDSM2(b[nf][0], b[nf][1],
                  bBase + nf * (8 * 128) + ((bCol0 + ks * 32) ^ mask));
#pragma unroll
        for (int mf = 0; mf < 4; mf++)
#pragma unroll
            for (int nf = 0; nf < 4; nf++)
                MMA_F16(acc[mf][nf], a[mf], b[nf]);
    }
}

// qkv: grid (2, 512) = (ntile, mtile). One CTA emits Q,K,V 128x256 tiles.
__global__ __launch_bounds__(512, 1)
void qkv_mma() {
    extern __shared__ char smc[];
    uint32_t smem = smem_u32(smc);
    const int ntile = blockIdx.x;
    const int m0    = blockIdx.y * 128;

    const __half* A     = g_x16 + (size_t)m0 * CDIM;
    const __half* Wbase = g_w16 + (size_t)(ntile * 256) * CDIM;
    const size_t  wstr  = (size_t)CDIM * CDIM;

    float acc[4][4][4];
#pragma unroll
    for (int mf = 0; mf < 4; mf++)
#pragma unroll
        for (int nf = 0; nf < 4; nf++)
#pragma unroll
            for (int r = 0; r < 4; r++) acc[mf][nf][r] = 0.f;

    fused_prefetch(smem, A, Wbase, wstr, 0);
    fused_prefetch(smem, A, Wbase, wstr, 1);

    const int tid = threadIdx.x, wid = tid >> 5, lane = tid & 31;
    const int wm = wid >> 3, wn = wid & 7;
    const int g8 = lane >> 2, tg = lane & 3;

    const int NTOT = 24;
    for (int g = 0; g < NTOT; g++) {
        CP_WAIT1();
        __syncthreads();
        if (g + 2 < NTOT) fused_prefetch(smem, A, Wbase, wstr, g + 2);
        else              CP_COMMIT();
        fused_compute(smem, g & 7, g % 3, acc);

        if ((g & 7) == 7) {
            const int wsel = g >> 3;
            __half* Out = (wsel == 0) ? g_q16 : (wsel == 1) ? g_k16 : g_v16;
            const float mul = (wsel == 0) ? 0.125f : 1.0f;
#pragma unroll
            for (int mf = 0; mf < 4; mf++) {
                const int r0 = m0 + wm * 64 + mf * 16 + g8;
#pragma unroll
                for (int nf = 0; nf < 4; nf++) {
                    const int col = ntile * 256 + wn * 32 + nf * 8 + 2 * tg;
                    *(uint32_t*)(Out + (size_t)r0 * CDIM + col) =
                        pkh(acc[mf][nf][0] * mul, acc[mf][nf][1] * mul);
                    *(uint32_t*)(Out + (size_t)(r0 + 8) * CDIM + col) =
                        pkh(acc[mf][nf][2] * mul, acc[mf][nf][3] * mul);
                    acc[mf][nf][0] = acc[mf][nf][1] = 0.f;
                    acc[mf][nf][2] = acc[mf][nf][3] = 0.f;
                }
            }
        }
    }
    CP_WAIT0();
}

// proj: grid (512) = mtile. One CTA emits both 256-wide halves of y rows.
__global__ __launch_bounds__(512, 1)
void proj_mma(const float* __restrict__ bo, float* __restrict__ y) {
    extern __shared__ char smc[];
    uint32_t smem = smem_u32(smc);
    const int m0 = blockIdx.x * 128;

    const __half* A     = g_ao + (size_t)m0 * CDIM;
    const __half* Wbase = g_w16 + (size_t)3 * CDIM * CDIM;   // Wo
    const size_t  wstr  = (size_t)256 * CDIM;                // half-matrix stride

    float acc[4][4][4];
#pragma unroll
    for (int mf = 0; mf < 4; mf++)
#pragma unroll
        for (int nf = 0; nf < 4; nf++)
#pragma unroll
            for (int r = 0; r < 4; r++) acc[mf][nf][r] = 0.f;

    fused_prefetch(smem, A, Wbase, wstr, 0);
    fused_prefetch(smem, A, Wbase, wstr, 1);

    const int tid = threadIdx.x, wid = tid >> 5, lane = tid & 31;
    const int wm = wid >> 3, wn = wid & 7;
    const int g8 = lane >> 2, tg = lane & 3;

    const int NTOT = 16;
    for (int g = 0; g < NTOT; g++) {
        CP_WAIT1();
        __syncthreads();
        if (g + 2 < NTOT) fused_prefetch(smem, A, Wbase, wstr, g + 2);
        else              CP_COMMIT();
        fused_compute(smem, g & 7, g % 3, acc);

        if ((g & 7) == 7) {
            const int nsel = g >> 3;
#pragma unroll
            for (int mf = 0; mf < 4; mf++) {
                const int r0 = m0 + wm * 64 + mf * 16 + g8;
                const int n0 = win_to_src(r0);
                const int n1 = win_to_src(r0 + 8);
#pragma unroll
                for (int nf = 0; nf < 4; nf++) {
                    const int col = nsel * 256 + wn * 32 + nf * 8 + 2 * tg;
                    const float b0 = bo[col], b1 = bo[col + 1];
                    *(float2*)(y + (size_t)n0 * CDIM + col) =
                        make_float2(acc[mf][nf][0] + b0, acc[mf][nf][1] + b1);
                    *(float2*)(y + (size_t)n1 * CDIM + col) =
                        make_float2(acc[mf][nf][2] + b0, acc[mf][nf][3] + b1);
                    acc[mf][nf][0] = acc[mf][nf][1] = 0.f;
                    acc[mf][nf][2] = acc[mf][nf][3] = 0.f;
                }
            }
        }
    }
    CP_WAIT0();
}

// =====================================================================
// attention (round-6 v2, unchanged): warp-owns-rows, register softmax.
// =====================================================================
#define ASTRIDE 144
#define QS_OFF  0
#define KS_OFF  (128 * ASTRIDE)
#define VS_OFF  (2 * 128 * ASTRIDE)
#define ATTN_SMEM_BYTES (3 * 128 * ASTRIDE)   // 55296

__global__ __launch_bounds__(256, 2)
void attn_mma() {
    extern __shared__ char smc[];
    uint32_t smem = smem_u32(smc);
    const int tid  = threadIdx.x;
    const int wid  = tid >> 5;
    const int lane = tid & 31;
    const int win = blockIdx.x >> 3;
    const int h   = blockIdx.x & 7;

    const size_t base = (size_t)(win * LWIN) * CDIM + h * HDIM;
#pragma unroll
    for (int i = 0; i < 4; i++) {
        int idx = tid + i * 256;
        int row = idx >> 3, c8 = idx & 7;
        size_t go = base + (size_t)row * CDIM + c8 * 8;
        uint32_t so = row * ASTRIDE + c8 * 16;
        *(uint4*)(smc + QS_OFF + so) = *(const uint4*)(g_q16 + go);
        *(uint4*)(smc + KS_OFF + so) = *(const uint4*)(g_k16 + go);
        *(uint4*)(smc + VS_OFF + so) = *(const uint4*)(g_v16 + go);
    }
    __syncthreads();

    float s[16][4];
#pragma unroll
    for (int nf = 0; nf < 16; nf++)
#pragma unroll
        for (int r = 0; r < 4; r++) s[nf][r] = 0.f;

    const uint32_t aLane = smem + QS_OFF
        + (uint32_t)(wid * 16 + (lane & 15)) * ASTRIDE + (lane >> 4) * 16;
    const uint32_t bBase = smem + KS_OFF
        + (uint32_t)((lane & 7) + ((lane >> 4) & 1) * 8) * ASTRIDE
        + ((lane >> 3) & 1) * 16;

#pragma unroll
    for (int ks = 0; ks < 4; ks++) {
        uint32_t a[4];
        LDSM4(a[0], a[1], a[2], a[3], aLane + ks * 32);
#pragma unroll
        for (int nfp = 0; nfp < 8; nfp++) {
            uint32_t b[4];
            LDSM4(b[0], b[1], b[2], b[3], bBase + nfp * (16 * ASTRIDE) + ks * 32);
            MMA_F16(s[2 * nfp],     a, b);
            MMA_F16(s[2 * nfp + 1], a, b + 2);
        }
    }

    float mx0 = -1e30f, mx1 = -1e30f;
#pragma unroll
    for (int nf = 0; nf < 16; nf++) {
        mx0 = fmaxf(mx0, fmaxf(s[nf][0], s[nf][1]));
        mx1 = fmaxf(mx1, fmaxf(s[nf][2], s[nf][3]));
    }
    mx0 = fmaxf(mx0, __shfl_xor_sync(0xffffffff, mx0, 1));
    mx0 = fmaxf(mx0, __shfl_xor_sync(0xffffffff, mx0, 2));
    mx1 = fmaxf(mx1, __shfl_xor_sync(0xffffffff, mx1, 1));
    mx1 = fmaxf(mx1, __shfl_xor_sync(0xffffffff, mx1, 2));

    float s0 = 0.f, s1 = 0.f;
#pragma unroll
    for (int nf = 0; nf < 16; nf++) {
        s[nf][0] = __expf(s[nf][0] - mx0);
        s[nf][1] = __expf(s[nf][1] - mx0);
        s[nf][2] = __expf(s[nf][2] - mx1);
        s[nf][3] = __expf(s[nf][3] - mx1);
        s0 += s[nf][0] + s[nf][1];
        s1 += s[nf][2] + s[nf][3];
    }
    s0 += __shfl_xor_sync(0xffffffff, s0, 1);
    s0 += __shfl_xor_sync(0xffffffff, s0, 2);
    s1 += __shfl_xor_sync(0xffffffff, s1, 1);
    s1 += __shfl_xor_sync(0xffffffff, s1, 2);
    const float inv0 = 1.f / s0, inv1 = 1.f / s1;

    uint32_t aP[8][4];
#pragma unroll
    for (int j = 0; j < 8; j++) {
        aP[j][0] = pkh(s[2 * j][0]     * inv0, s[2 * j][1]     * inv0);
        aP[j][1] = pkh(s[2 * j][2]     * inv1, s[2 * j][3]     * inv1);
        aP[j][2] = pkh(s[2 * j + 1][0] * inv0, s[2 * j + 1][1] * inv0);
        aP[j][3] = pkh(s[2 * j + 1][2] * inv1, s[2 * j + 1][3] * inv1);
    }

    float o[8][4];
#pragma unroll
    for (int nf = 0; nf < 8; nf++)
#pragma unroll
        for (int r = 0; r < 4; r++) o[nf][r] = 0.f;

    const uint32_t vBase = smem + VS_OFF
        + (uint32_t)((lane & 7) + ((lane >> 3) & 1) * 8) * ASTRIDE
        + ((lane >> 4) & 1) * 16;

#pragma unroll
    for (int j = 0; j < 8; j++) {
#pragma unroll
        for (int nfp = 0; nfp < 4; nfp++) {
            uint32_t b[4];
            LDSM4T(b[0], b[1], b[2], b[3], vBase + j * (16 * ASTRIDE) + nfp * 32);
            MMA_F16(o[2 * nfp],     aP[j], b);
            MMA_F16(o[2 * nfp + 1], aP[j], b + 2);
        }
    }

    const int g = lane >> 2, tg = lane & 3;
    const int m0 = win * LWIN + wid * 16;
#pragma unroll
    for (int nf = 0; nf < 8; nf++) {
        const int col = h * HDIM + nf * 8 + 2 * tg;
        *(uint32_t*)(g_ao + (size_t)(m0 + g) * CDIM + col)     = pkh(o[nf][0], o[nf][1]);
        *(uint32_t*)(g_ao + (size_t)(m0 + g + 8) * CDIM + col) = pkh(o[nf][2], o[nf][3]);
    }
}

// =====================================================================
// launcher
// =====================================================================
extern "C" void kernel_launch(void* const* d_in, const int* in_sizes, int n_in,
                              void* d_out, int out_size)
{
    (void)in_sizes; (void)n_in; (void)out_size;
    const float* x  = (const float*)d_in[0];
    const float* Wq = (const float*)d_in[1];
    const float* Wk = (const float*)d_in[2];
    const float* Wv = (const float*)d_in[3];
    const float* Wo = (const float*)d_in[4];
    const float* bo = (const float*)d_in[5];
    float* y = (float*)d_out;

    cudaFuncSetAttribute(qkv_mma,  cudaFuncAttributeMaxDynamicSharedMemorySize, FUSED_SMEM_BYTES);
    cudaFuncSetAttribute(proj_mma, cudaFuncAttributeMaxDynamicSharedMemorySize, FUSED_SMEM_BYTES);
    cudaFuncSetAttribute(attn_mma, cudaFuncAttributeMaxDynamicSharedMemorySize, ATTN_SMEM_BYTES);

    convert_w<<<1024, 256>>>(Wq, Wk, Wv, Wo);
    convert_x<<<32768, 256>>>(x);
    qkv_mma<<<dim3(2, 512), 512, FUSED_SMEM_BYTES>>>();
    attn_mma<<<NWIN * NHEAD, 256, ATTN_SMEM_BYTES>>>();
    proj_mma<<<512, 512, FUSED_SMEM_BYTES>>>(bo, y);
}